// round 6
// baseline (speedup 1.0000x reference)
#include <cuda_runtime.h>
#include <cuda_bf16.h>

// CompetitiveLayer: 21 iterations of
//   AF = AT / (1 + K @ BF)        (row matvec,   K = param^2)
//   BF = BT / (1 + AF @ K)        (col matvec)
// then C = K * AF[:,None] * BF[None,:]
//
// N = 4096. K (64 MB fp32) is L2-resident after the first pass; the kernel
// sequence is tuned to stream K from L2 at full LTS throughput.

#define N        4096
#define NF4      (N / 4)          // 1024 float4 per row
#define NITER    21
#define ROW_CHUNKS 8              // col-matvec row split (deterministic 2-stage reduce)
#define CHUNK_ROWS (N / ROW_CHUNKS)   // 512

// Scratch (no cudaMalloc allowed)
__device__ float g_AF[N];
__device__ float g_BF[N];
__device__ float g_tmp[ROW_CHUNKS * N];

// ---------------------------------------------------------------------------
// Row matvec: AF[i] = AT[i] / (1 + sum_j param[i][j]^2 * BF[j])
// 1 warp per row, 8 rows per 256-thread block, BF staged in shared once/block.
// grid = 512 blocks.
// ---------------------------------------------------------------------------
__global__ __launch_bounds__(256, 2)
void row_mv_kernel(const float* __restrict__ P,
                   const float* __restrict__ AT,
                   const float* __restrict__ BT,
                   int use_bt)
{
    __shared__ float4 sBF[NF4];   // 16 KB

    const int tid  = threadIdx.x;
    const float* BFin = use_bt ? BT : g_BF;
    const float4* bf4 = reinterpret_cast<const float4*>(BFin);

    #pragma unroll
    for (int i = tid; i < NF4; i += 256) sBF[i] = bf4[i];
    __syncthreads();

    const int warp = tid >> 5;
    const int lane = tid & 31;
    const int row  = blockIdx.x * 8 + warp;

    const float4* prow = reinterpret_cast<const float4*>(P + ((size_t)row << 12));

    float4 acc = make_float4(0.f, 0.f, 0.f, 0.f);
    #pragma unroll 8
    for (int j = lane; j < NF4; j += 32) {
        float4 p = prow[j];
        float4 b = sBF[j];
        acc.x = fmaf(p.x * p.x, b.x, acc.x);
        acc.y = fmaf(p.y * p.y, b.y, acc.y);
        acc.z = fmaf(p.z * p.z, b.z, acc.z);
        acc.w = fmaf(p.w * p.w, b.w, acc.w);
    }
    float s = (acc.x + acc.y) + (acc.z + acc.w);
    #pragma unroll
    for (int o = 16; o > 0; o >>= 1) s += __shfl_xor_sync(0xFFFFFFFFu, s, o);

    if (lane == 0) g_AF[row] = AT[row] / (1.0f + s);
}

// ---------------------------------------------------------------------------
// Col matvec partial: tmp[chunk][j] = sum_{i in chunk} AF[i] * param[i][j]^2
// grid = (32 col-tiles of 128 cols, 8 row-chunks of 512 rows) = 256 blocks.
// Block: 8 warps = 8 row lanes; each lane owns 4 consecutive cols via float4.
// ---------------------------------------------------------------------------
__global__ __launch_bounds__(256, 2)
void col_mv_partial_kernel(const float* __restrict__ P)
{
    __shared__ float  sAF[CHUNK_ROWS];      // 2 KB
    __shared__ float4 sAcc[8][32];          // 4 KB

    const int tid     = threadIdx.x;
    const int warp    = tid >> 5;
    const int lane    = tid & 31;
    const int colBase = blockIdx.x * 128;
    const int rowBase = blockIdx.y * CHUNK_ROWS;

    for (int i = tid; i < CHUNK_ROWS; i += 256) sAF[i] = g_AF[rowBase + i];
    __syncthreads();

    float4 acc = make_float4(0.f, 0.f, 0.f, 0.f);
    #pragma unroll 4
    for (int k = 0; k < CHUNK_ROWS / 8; k++) {
        const int r = warp + 8 * k;               // 0..511, per-warp row stream
        const float a = sAF[r];
        const float4 p = *reinterpret_cast<const float4*>(
            P + (((size_t)(rowBase + r)) << 12) + colBase + 4 * lane);
        acc.x = fmaf(a * p.x, p.x, acc.x);
        acc.y = fmaf(a * p.y, p.y, acc.y);
        acc.z = fmaf(a * p.z, p.z, acc.z);
        acc.w = fmaf(a * p.w, p.w, acc.w);
    }
    sAcc[warp][lane] = acc;
    __syncthreads();

    // Deterministic cross-warp reduce: thread t (<128) owns col colBase+t.
    // Flattened float index inside sAcc[w] equals the in-tile col index.
    if (tid < 128) {
        float s = 0.f;
        #pragma unroll
        for (int w = 0; w < 8; w++) {
            const float* rowv = reinterpret_cast<const float*>(sAcc[w]);
            s += rowv[tid];
        }
        g_tmp[blockIdx.y * N + colBase + tid] = s;
    }
}

// ---------------------------------------------------------------------------
// Finalize: BF[j] = BT[j] / (1 + sum_chunks tmp[chunk][j]).  grid = 16 x 256.
// ---------------------------------------------------------------------------
__global__ __launch_bounds__(256, 4)
void finalize_bf_kernel(const float* __restrict__ BT)
{
    const int j = blockIdx.x * 256 + threadIdx.x;
    float s = 0.f;
    #pragma unroll
    for (int c = 0; c < ROW_CHUNKS; c++) s += g_tmp[c * N + j];
    g_BF[j] = BT[j] / (1.0f + s);
}

// ---------------------------------------------------------------------------
// Output: C[i][j] = param[i][j]^2 * AF[i] * BF[j].  One float4 per thread.
// grid = 16384 x 256.
// ---------------------------------------------------------------------------
__global__ __launch_bounds__(256, 4)
void compute_c_kernel(const float* __restrict__ P, float* __restrict__ C)
{
    const size_t idx = (size_t)blockIdx.x * 256 + threadIdx.x;  // float4 index
    const int row  = (int)(idx >> 10);          // /1024 float4 per row
    const int col4 = (int)(idx & 1023);

    const float a  = g_AF[row];
    const float4 p = reinterpret_cast<const float4*>(P)[idx];
    const float4 b = *reinterpret_cast<const float4*>(&g_BF[col4 * 4]);

    float4 o;
    o.x = p.x * p.x * a * b.x;
    o.y = p.y * p.y * a * b.y;
    o.z = p.z * p.z * a * b.z;
    o.w = p.w * p.w * a * b.w;
    reinterpret_cast<float4*>(C)[idx] = o;
}

// ---------------------------------------------------------------------------
// Launch: 21 x {rowMV, colMV-partial, finalize} + C.  64 graph nodes, all on
// the default stream (graph-capturable; no sync, no alloc, no memcpy).
// ---------------------------------------------------------------------------
extern "C" void kernel_launch(void* const* d_in, const int* in_sizes, int n_in,
                              void* d_out, int out_size)
{
    const float* AT = (const float*)d_in[0];   // [4096]
    const float* BT = (const float*)d_in[1];   // [4096]
    const float* P  = (const float*)d_in[2];   // [4096, 4096]
    float* C = (float*)d_out;                  // [4096, 4096]

    const dim3 colGrid(N / 128, ROW_CHUNKS);   // (32, 8)

    for (int it = 0; it < NITER; it++) {
        row_mv_kernel<<<N / 8, 256>>>(P, AT, BT, it == 0 ? 1 : 0);
        col_mv_partial_kernel<<<colGrid, 256>>>(P);
        finalize_bf_kernel<<<N / 256, 256>>>(BT);
    }
    compute_c_kernel<<<(N * NF4) / 256, 256>>>(P, C);
}

// round 7
// speedup vs baseline: 1.0222x; 1.0222x over previous
#include <cuda_runtime.h>
#include <cuda_bf16.h>

// CompetitiveLayer: 21 iterations of
//   AF = AT / (1 + K @ BF)        (row matvec,   K = param^2)
//   BF = BT / (1 + AF @ K)        (col matvec)
// then C = K * AF[:,None] * BF[None,:]
//
// N = 4096. K (64 MB fp32) is L2-resident after the first pass; the kernel
// sequence is tuned to stream K from L2 at full LTS throughput.

#define N        4096
#define NF4      (N / 4)          // 1024 float4 per row
#define NITER    21
#define ROW_CHUNKS 8              // col-matvec row split (deterministic 2-stage reduce)
#define CHUNK_ROWS (N / ROW_CHUNKS)   // 512

// Scratch (no cudaMalloc allowed)
__device__ float g_AF[N];
__device__ float g_BF[N];
__device__ float g_tmp[ROW_CHUNKS * N];

// ---------------------------------------------------------------------------
// Row matvec: AF[i] = AT[i] / (1 + sum_j param[i][j]^2 * BF[j])
// 1 warp per row, 8 rows per 256-thread block, BF staged in shared once/block.
// grid = 512 blocks.
// ---------------------------------------------------------------------------
__global__ __launch_bounds__(256, 2)
void row_mv_kernel(const float* __restrict__ P,
                   const float* __restrict__ AT,
                   const float* __restrict__ BT,
                   int use_bt)
{
    __shared__ float4 sBF[NF4];   // 16 KB

    const int tid  = threadIdx.x;
    const float* BFin = use_bt ? BT : g_BF;
    const float4* bf4 = reinterpret_cast<const float4*>(BFin);

    #pragma unroll
    for (int i = tid; i < NF4; i += 256) sBF[i] = bf4[i];
    __syncthreads();

    const int warp = tid >> 5;
    const int lane = tid & 31;
    const int row  = blockIdx.x * 8 + warp;

    const float4* prow = reinterpret_cast<const float4*>(P + ((size_t)row << 12));

    float4 acc = make_float4(0.f, 0.f, 0.f, 0.f);
    #pragma unroll 8
    for (int j = lane; j < NF4; j += 32) {
        float4 p = prow[j];
        float4 b = sBF[j];
        acc.x = fmaf(p.x * p.x, b.x, acc.x);
        acc.y = fmaf(p.y * p.y, b.y, acc.y);
        acc.z = fmaf(p.z * p.z, b.z, acc.z);
        acc.w = fmaf(p.w * p.w, b.w, acc.w);
    }
    float s = (acc.x + acc.y) + (acc.z + acc.w);
    #pragma unroll
    for (int o = 16; o > 0; o >>= 1) s += __shfl_xor_sync(0xFFFFFFFFu, s, o);

    if (lane == 0) g_AF[row] = AT[row] / (1.0f + s);
}

// ---------------------------------------------------------------------------
// Col matvec partial: tmp[chunk][j] = sum_{i in chunk} AF[i] * param[i][j]^2
// grid = (32 col-tiles of 128 cols, 8 row-chunks of 512 rows) = 256 blocks.
// Block: 8 warps = 8 row lanes; each lane owns 4 consecutive cols via float4.
// ---------------------------------------------------------------------------
__global__ __launch_bounds__(256, 2)
void col_mv_partial_kernel(const float* __restrict__ P)
{
    __shared__ float  sAF[CHUNK_ROWS];      // 2 KB
    __shared__ float4 sAcc[8][32];          // 4 KB

    const int tid     = threadIdx.x;
    const int warp    = tid >> 5;
    const int lane    = tid & 31;
    const int colBase = blockIdx.x * 128;
    const int rowBase = blockIdx.y * CHUNK_ROWS;

    for (int i = tid; i < CHUNK_ROWS; i += 256) sAF[i] = g_AF[rowBase + i];
    __syncthreads();

    float4 acc = make_float4(0.f, 0.f, 0.f, 0.f);
    #pragma unroll 4
    for (int k = 0; k < CHUNK_ROWS / 8; k++) {
        const int r = warp + 8 * k;               // 0..511, per-warp row stream
        const float a = sAF[r];
        const float4 p = *reinterpret_cast<const float4*>(
            P + (((size_t)(rowBase + r)) << 12) + colBase + 4 * lane);
        acc.x = fmaf(a * p.x, p.x, acc.x);
        acc.y = fmaf(a * p.y, p.y, acc.y);
        acc.z = fmaf(a * p.z, p.z, acc.z);
        acc.w = fmaf(a * p.w, p.w, acc.w);
    }
    sAcc[warp][lane] = acc;
    __syncthreads();

    // Deterministic cross-warp reduce: thread t (<128) owns col colBase+t.
    // Flattened float index inside sAcc[w] equals the in-tile col index.
    if (tid < 128) {
        float s = 0.f;
        #pragma unroll
        for (int w = 0; w < 8; w++) {
            const float* rowv = reinterpret_cast<const float*>(sAcc[w]);
            s += rowv[tid];
        }
        g_tmp[blockIdx.y * N + colBase + tid] = s;
    }
}

// ---------------------------------------------------------------------------
// Finalize: BF[j] = BT[j] / (1 + sum_chunks tmp[chunk][j]).  grid = 16 x 256.
// ---------------------------------------------------------------------------
__global__ __launch_bounds__(256, 4)
void finalize_bf_kernel(const float* __restrict__ BT)
{
    const int j = blockIdx.x * 256 + threadIdx.x;
    float s = 0.f;
    #pragma unroll
    for (int c = 0; c < ROW_CHUNKS; c++) s += g_tmp[c * N + j];
    g_BF[j] = BT[j] / (1.0f + s);
}

// ---------------------------------------------------------------------------
// Output: C[i][j] = param[i][j]^2 * AF[i] * BF[j].  One float4 per thread.
// grid = 16384 x 256.
// ---------------------------------------------------------------------------
__global__ __launch_bounds__(256, 4)
void compute_c_kernel(const float* __restrict__ P, float* __restrict__ C)
{
    const size_t idx = (size_t)blockIdx.x * 256 + threadIdx.x;  // float4 index
    const int row  = (int)(idx >> 10);          // /1024 float4 per row
    const int col4 = (int)(idx & 1023);

    const float a  = g_AF[row];
    const float4 p = reinterpret_cast<const float4*>(P)[idx];
    const float4 b = *reinterpret_cast<const float4*>(&g_BF[col4 * 4]);

    float4 o;
    o.x = p.x * p.x * a * b.x;
    o.y = p.y * p.y * a * b.y;
    o.z = p.z * p.z * a * b.z;
    o.w = p.w * p.w * a * b.w;
    reinterpret_cast<float4*>(C)[idx] = o;
}

// ---------------------------------------------------------------------------
// Launch: 21 x {rowMV, colMV-partial, finalize} + C.  64 graph nodes, all on
// the default stream (graph-capturable; no sync, no alloc, no memcpy).
// ---------------------------------------------------------------------------
extern "C" void kernel_launch(void* const* d_in, const int* in_sizes, int n_in,
                              void* d_out, int out_size)
{
    const float* AT = (const float*)d_in[0];   // [4096]
    const float* BT = (const float*)d_in[1];   // [4096]
    const float* P  = (const float*)d_in[2];   // [4096, 4096]
    float* C = (float*)d_out;                  // [4096, 4096]

    const dim3 colGrid(N / 128, ROW_CHUNKS);   // (32, 8)

    for (int it = 0; it < NITER; it++) {
        row_mv_kernel<<<N / 8, 256>>>(P, AT, BT, it == 0 ? 1 : 0);
        col_mv_partial_kernel<<<colGrid, 256>>>(P);
        finalize_bf_kernel<<<N / 256, 256>>>(BT);
    }
    compute_c_kernel<<<(N * NF4) / 256, 256>>>(P, C);
}

// round 8
// speedup vs baseline: 1.1217x; 1.0973x over previous
#include <cuda_runtime.h>
#include <cuda_fp16.h>

// CompetitiveLayer: 21 iterations of
//   AF = AT / (1 + K @ BF),  BF = BT / (1 + AF @ K),  K = param^2
// then C = K * AF[:,None] * BF[None,:].
//
// N = 4096. Strategy: build a one-time fp16 copy of K^2 (32 MB, L2-resident)
// and stream THAT 42x instead of the 64 MB fp32 K — halves L2 traffic in the
// bandwidth-bound iteration phase. The final C uses exact fp32 param^2, so
// fp16 rounding only perturbs AF/BF (~1e-5 rel), far under the 1e-3 gate.

#define N        4096
#define NITER    21
#define ROW_CHUNKS 16             // col-matvec row split
#define CHUNK_ROWS (N / ROW_CHUNKS)   // 256
#define COL_TILE   256            // cols per col-matvec block

// Scratch (no cudaMalloc allowed) — __device__ globals
__device__ __half g_Kh[(size_t)N * N];   // fp16 copy of param^2 (32 MB)
__device__ float  g_AF[N];
__device__ float  g_BF[N];
__device__ float  g_tmp[ROW_CHUNKS * N];

// ---------------------------------------------------------------------------
// Prep: g_Kh[i][j] = (half)(P[i][j]^2).  One thread = 8 elements.
// grid = 8192 x 256.
// ---------------------------------------------------------------------------
__global__ __launch_bounds__(256, 4)
void prep_kh_kernel(const float* __restrict__ P)
{
    const size_t idx = (size_t)blockIdx.x * 256 + threadIdx.x;  // unit: 8 floats
    const float4* p4 = reinterpret_cast<const float4*>(P);
    float4 a = p4[2 * idx];
    float4 b = p4[2 * idx + 1];

    __half2 h0 = __floats2half2_rn(a.x * a.x, a.y * a.y);
    __half2 h1 = __floats2half2_rn(a.z * a.z, a.w * a.w);
    __half2 h2 = __floats2half2_rn(b.x * b.x, b.y * b.y);
    __half2 h3 = __floats2half2_rn(b.z * b.z, b.w * b.w);

    uint4 out;
    out.x = *reinterpret_cast<unsigned*>(&h0);
    out.y = *reinterpret_cast<unsigned*>(&h1);
    out.z = *reinterpret_cast<unsigned*>(&h2);
    out.w = *reinterpret_cast<unsigned*>(&h3);
    reinterpret_cast<uint4*>(g_Kh)[idx] = out;
}

// ---------------------------------------------------------------------------
// Row matvec: AF[i] = AT[i] / (1 + sum_j Kh[i][j] * BF[j])
// 1 warp per row (8 rows / 256-thread block), BF staged in shared (fp32).
// Lane loads uint4 = 8 halves. grid = 512 blocks.
// ---------------------------------------------------------------------------
__global__ __launch_bounds__(256, 2)
void row_mv_kernel(const float* __restrict__ AT,
                   const float* __restrict__ BT,
                   int use_bt)
{
    __shared__ float sBF[N];   // 16 KB

    const int tid = threadIdx.x;
    const float* BFin = use_bt ? BT : g_BF;
    const float4* bf4 = reinterpret_cast<const float4*>(BFin);
    float4* sbf4 = reinterpret_cast<float4*>(sBF);
    #pragma unroll
    for (int i = tid; i < N / 4; i += 256) sbf4[i] = bf4[i];
    __syncthreads();

    const int warp = tid >> 5;
    const int lane = tid & 31;
    const int row  = blockIdx.x * 8 + warp;

    const uint4* prow = reinterpret_cast<const uint4*>(g_Kh + ((size_t)row << 12));

    float acc = 0.f;
    #pragma unroll 8
    for (int j = lane; j < N / 8; j += 32) {      // 16 trips, 16B each
        uint4 v = prow[j];
        const float* b = &sBF[j * 8];
        float2 f0 = __half22float2(*reinterpret_cast<__half2*>(&v.x));
        float2 f1 = __half22float2(*reinterpret_cast<__half2*>(&v.y));
        float2 f2 = __half22float2(*reinterpret_cast<__half2*>(&v.z));
        float2 f3 = __half22float2(*reinterpret_cast<__half2*>(&v.w));
        acc = fmaf(f0.x, b[0], acc);
        acc = fmaf(f0.y, b[1], acc);
        acc = fmaf(f1.x, b[2], acc);
        acc = fmaf(f1.y, b[3], acc);
        acc = fmaf(f2.x, b[4], acc);
        acc = fmaf(f2.y, b[5], acc);
        acc = fmaf(f3.x, b[6], acc);
        acc = fmaf(f3.y, b[7], acc);
    }
    #pragma unroll
    for (int o = 16; o > 0; o >>= 1) acc += __shfl_xor_sync(0xFFFFFFFFu, acc, o);

    if (lane == 0) g_AF[row] = AT[row] / (1.0f + acc);
}

// ---------------------------------------------------------------------------
// Col matvec partial: tmp[chunk][j] = sum_{i in chunk} AF[i] * Kh[i][j]
// grid = (N/COL_TILE = 16, ROW_CHUNKS = 16) = 256 blocks.
// Block: 8 warps stride rows; each lane owns 8 consecutive cols (uint4 load).
// Deterministic 2-stage reduce: shared cross-warp, then g_tmp, then finalize.
// ---------------------------------------------------------------------------
__global__ __launch_bounds__(256, 4)
void col_mv_partial_kernel()
{
    __shared__ float sAF[CHUNK_ROWS];     // 1 KB
    __shared__ float sAcc[8][COL_TILE];   // 8 KB

    const int tid     = threadIdx.x;
    const int warp    = tid >> 5;
    const int lane    = tid & 31;
    const int colBase = blockIdx.x * COL_TILE;
    const int rowBase = blockIdx.y * CHUNK_ROWS;

    if (tid < CHUNK_ROWS) sAF[tid] = g_AF[rowBase + tid];
    __syncthreads();

    float acc[8];
    #pragma unroll
    for (int k = 0; k < 8; k++) acc[k] = 0.f;

    #pragma unroll 4
    for (int s = 0; s < CHUNK_ROWS / 8; s++) {    // 32 trips
        const int r = warp + 8 * s;
        const float a = sAF[r];
        uint4 v = *reinterpret_cast<const uint4*>(
            g_Kh + (((size_t)(rowBase + r)) << 12) + colBase + 8 * lane);
        float2 f0 = __half22float2(*reinterpret_cast<__half2*>(&v.x));
        float2 f1 = __half22float2(*reinterpret_cast<__half2*>(&v.y));
        float2 f2 = __half22float2(*reinterpret_cast<__half2*>(&v.z));
        float2 f3 = __half22float2(*reinterpret_cast<__half2*>(&v.w));
        acc[0] = fmaf(a, f0.x, acc[0]);
        acc[1] = fmaf(a, f0.y, acc[1]);
        acc[2] = fmaf(a, f1.x, acc[2]);
        acc[3] = fmaf(a, f1.y, acc[3]);
        acc[4] = fmaf(a, f2.x, acc[4]);
        acc[5] = fmaf(a, f2.y, acc[5]);
        acc[6] = fmaf(a, f3.x, acc[6]);
        acc[7] = fmaf(a, f3.y, acc[7]);
    }

    #pragma unroll
    for (int k = 0; k < 8; k++) sAcc[warp][lane * 8 + k] = acc[k];
    __syncthreads();

    // thread t (<256) owns col colBase + t; fixed-order sum over 8 warps.
    float s = 0.f;
    #pragma unroll
    for (int w = 0; w < 8; w++) s += sAcc[w][tid];
    g_tmp[blockIdx.y * N + colBase + tid] = s;
}

// ---------------------------------------------------------------------------
// Finalize: BF[j] = BT[j] / (1 + sum_chunks tmp[chunk][j]).  grid = 16 x 256.
// ---------------------------------------------------------------------------
__global__ __launch_bounds__(256, 4)
void finalize_bf_kernel(const float* __restrict__ BT)
{
    const int j = blockIdx.x * 256 + threadIdx.x;
    float s = 0.f;
    #pragma unroll
    for (int c = 0; c < ROW_CHUNKS; c++) s += g_tmp[c * N + j];
    g_BF[j] = BT[j] / (1.0f + s);
}

// ---------------------------------------------------------------------------
// Output: C[i][j] = param[i][j]^2 * AF[i] * BF[j]  — exact fp32 K here.
// One float4 per thread. grid = 16384 x 256.
// ---------------------------------------------------------------------------
__global__ __launch_bounds__(256, 4)
void compute_c_kernel(const float* __restrict__ P, float* __restrict__ C)
{
    const size_t idx = (size_t)blockIdx.x * 256 + threadIdx.x;  // float4 index
    const int row  = (int)(idx >> 10);
    const int col4 = (int)(idx & 1023);

    const float a  = g_AF[row];
    const float4 p = reinterpret_cast<const float4*>(P)[idx];
    const float4 b = *reinterpret_cast<const float4*>(&g_BF[col4 * 4]);

    float4 o;
    o.x = p.x * p.x * a * b.x;
    o.y = p.y * p.y * a * b.y;
    o.z = p.z * p.z * a * b.z;
    o.w = p.w * p.w * a * b.w;
    reinterpret_cast<float4*>(C)[idx] = o;
}

// ---------------------------------------------------------------------------
// Launch: prep + 21 x {rowMV, colMV-partial, finalize} + C = 65 graph nodes.
// Default stream only; no sync, no alloc, no memcpy — graph-capturable.
// ---------------------------------------------------------------------------
extern "C" void kernel_launch(void* const* d_in, const int* in_sizes, int n_in,
                              void* d_out, int out_size)
{
    const float* AT = (const float*)d_in[0];   // [4096]
    const float* BT = (const float*)d_in[1];   // [4096]
    const float* P  = (const float*)d_in[2];   // [4096, 4096]
    float* C = (float*)d_out;                  // [4096, 4096]

    prep_kh_kernel<<<((size_t)N * N / 8) / 256, 256>>>(P);

    const dim3 colGrid(N / COL_TILE, ROW_CHUNKS);   // (16, 16)

    for (int it = 0; it < NITER; it++) {
        row_mv_kernel<<<N / 8, 256>>>(AT, BT, it == 0 ? 1 : 0);
        col_mv_partial_kernel<<<colGrid, 256>>>();
        finalize_bf_kernel<<<N / 256, 256>>>(BT);
    }
    compute_c_kernel<<<((size_t)N * (N / 4)) / 256, 256>>>(P, C);
}